// round 1
// baseline (speedup 1.0000x reference)
#include <cuda_runtime.h>
#include <math.h>

#define NB   2
#define NT   1024
#define ND   2048
#define NH   16
#define NDK  128
#define NTOK (NB*NT)      /* 2048 tokens */
#define NC   (NH*NDK)     /* 2048 channels */

// ------------------------------------------------------------------
// Scratch (device globals; no runtime allocation allowed)
// ------------------------------------------------------------------
__device__ float g_q0[NTOK*NC];   // raw projections (pre-conv)
__device__ float g_k0[NTOK*NC];
__device__ float g_v0[NTOK*NC];
__device__ float g_qc[NTOK*NC];   // post conv+silu
__device__ float g_kc[NTOK*NC];   // (includes DK^-0.5 scale)
__device__ float g_vc[NTOK*NC];
__device__ float g_a [NTOK*NC];   // sigmoid(x@Wa^T + ba)
__device__ float g_gt[NTOK*NC];   // sigmoid(x@Wg^T)
__device__ float g_bt[NTOK*NH];   // sigmoid(x@Wb^T + bb)
__device__ float g_og[NTOK*NC];   // gated, layernormed recurrence output

// ------------------------------------------------------------------
// GEMM: C[m,n] = epi( sum_k A[m,k] * W[n,k] (+ bias[n]) )
// A: [M,K] row-major, W: [N,K] row-major (i.e. C = A @ W^T)
// epi: 0 = identity, 1 = sigmoid(acc + bias)
// Tiles: BM=BN=128, BK=16; 256 threads; 8x8 micro-tile per thread.
// ------------------------------------------------------------------
#define BM 128
#define BN 128
#define BK 16

__global__ void __launch_bounds__(256, 2)
gemm_nt(const float* __restrict__ A, const float* __restrict__ W,
        const float* __restrict__ bias, float* __restrict__ C,
        int M, int N, int K, int epi)
{
    __shared__ float As[BK][BM + 4];
    __shared__ float Bs[BK][BN + 4];

    const int tid = threadIdx.x;
    const int tx  = tid & 15;   // n micro index
    const int ty  = tid >> 4;   // m micro index
    const int m0  = blockIdx.y * BM;
    const int n0  = blockIdx.x * BN;

    const int lrow = tid >> 2;  // 0..63  (row within 64-row half-tile)
    const int lc4  = tid & 3;   // 0..3   (which float4 in the 16-wide K slice)

    float acc[8][8];
#pragma unroll
    for (int i = 0; i < 8; i++)
#pragma unroll
        for (int j = 0; j < 8; j++) acc[i][j] = 0.f;

    const int nk = K / BK;
    for (int kt = 0; kt < nk; kt++) {
        const int k0 = kt * BK;
        // load A tile (128 rows x 16 cols) -> As[k][m]
#pragma unroll
        for (int r = 0; r < 2; r++) {
            int row = lrow + r * 64;
            int gm  = m0 + row;
            float4 v = make_float4(0.f, 0.f, 0.f, 0.f);
            if (gm < M)
                v = *reinterpret_cast<const float4*>(A + (size_t)gm * K + k0 + lc4 * 4);
            As[lc4*4+0][row] = v.x; As[lc4*4+1][row] = v.y;
            As[lc4*4+2][row] = v.z; As[lc4*4+3][row] = v.w;
        }
        // load W tile (128 rows x 16 cols) -> Bs[k][n]
#pragma unroll
        for (int r = 0; r < 2; r++) {
            int row = lrow + r * 64;
            int gn  = n0 + row;
            float4 v = make_float4(0.f, 0.f, 0.f, 0.f);
            if (gn < N)
                v = *reinterpret_cast<const float4*>(W + (size_t)gn * K + k0 + lc4 * 4);
            Bs[lc4*4+0][row] = v.x; Bs[lc4*4+1][row] = v.y;
            Bs[lc4*4+2][row] = v.z; Bs[lc4*4+3][row] = v.w;
        }
        __syncthreads();

#pragma unroll
        for (int kk = 0; kk < BK; kk++) {
            float a[8], b[8];
#pragma unroll
            for (int i = 0; i < 8; i++) a[i] = As[kk][ty * 8 + i];
#pragma unroll
            for (int j = 0; j < 8; j++) b[j] = Bs[kk][tx * 8 + j];
#pragma unroll
            for (int i = 0; i < 8; i++)
#pragma unroll
                for (int j = 0; j < 8; j++)
                    acc[i][j] = fmaf(a[i], b[j], acc[i][j]);
        }
        __syncthreads();
    }

#pragma unroll
    for (int i = 0; i < 8; i++) {
        int gm = m0 + ty * 8 + i;
        if (gm >= M) continue;
#pragma unroll
        for (int j = 0; j < 8; j++) {
            int gn = n0 + tx * 8 + j;
            if (gn >= N) continue;
            float val = acc[i][j];
            if (epi == 1) {
                float bb = bias ? bias[gn] : 0.f;
                val = 1.f / (1.f + expf(-(val + bb)));
            }
            C[(size_t)gm * N + gn] = val;
        }
    }
}

// ------------------------------------------------------------------
// Causal depthwise conv (K_CONV=4) + bias + silu + scale
// in/out: [B, T, NC]; w: [NC, 1, 4]
// out[b,t,c] = silu(bias[c] + sum_j w[c,j] * in[b, t-3+j, c]) * scale
// ------------------------------------------------------------------
__global__ void conv_silu(const float* __restrict__ in, const float* __restrict__ w,
                          const float* __restrict__ bias, float* __restrict__ out,
                          float scale)
{
    int idx = blockIdx.x * blockDim.x + threadIdx.x;
    if (idx >= NTOK * NC) return;
    int c  = idx & (NC - 1);
    int bt = idx >> 11;            // / 2048
    int t  = bt & (NT - 1);
    int b  = bt >> 10;             // / 1024

    const float4 wc = *reinterpret_cast<const float4*>(w + c * 4);
    const float* p  = in + ((size_t)b * NT) * NC + c;

    float acc = bias[c];
    if (t >= 3) acc = fmaf(wc.x, p[(size_t)(t - 3) * NC], acc);
    if (t >= 2) acc = fmaf(wc.y, p[(size_t)(t - 2) * NC], acc);
    if (t >= 1) acc = fmaf(wc.z, p[(size_t)(t - 1) * NC], acc);
    acc = fmaf(wc.w, p[(size_t)t * NC], acc);

    float s = acc / (1.f + expf(-acc));   // silu
    out[idx] = s * scale;
}

// ------------------------------------------------------------------
// Recurrence + fused LayerNorm + gate.
// Grid: B*H blocks, 128 threads (thread = v channel). S[v][0:128] in regs.
// Per step:  Sk = S@k; S = a*S - beta*(Sk - v) k^T; o = S@q; LN; *g
// ------------------------------------------------------------------
__global__ void __launch_bounds__(128)
recur_kernel(const float* __restrict__ qc, const float* __restrict__ kc,
             const float* __restrict__ vc, const float* __restrict__ ga,
             const float* __restrict__ gbeta, const float* __restrict__ gg,
             const float* __restrict__ ln_g, const float* __restrict__ ln_b,
             float* __restrict__ og)
{
    const int bh = blockIdx.x;
    const int b  = bh / NH;
    const int h  = bh % NH;
    const int v  = threadIdx.x;           // 0..127
    const int lane = v & 31, wid = v >> 5;

    float S[NDK];
#pragma unroll
    for (int j = 0; j < NDK; j++) S[j] = 0.f;

    __shared__ float sk[2][NDK];
    __shared__ float sq[2][NDK];
    __shared__ float red[8];

    const float lg = ln_g[v];
    const float lb = ln_b[v];
    const int chan = h * NDK + v;

    // preload t=0
    size_t idx0 = ((size_t)(b * NT)) * NC + chan;
    float k_cur = kc[idx0], q_cur = qc[idx0], v_cur = vc[idx0];
    float a_cur = ga[idx0], g_cur = gg[idx0];
    float beta_cur = gbeta[(size_t)(b * NT) * NH + h];

    for (int t = 0; t < NT; t++) {
        const int buf = t & 1;
        sk[buf][v] = k_cur;
        sq[buf][v] = q_cur;
        __syncthreads();

        // prefetch t+1 (hides L2 latency behind the FMA chain)
        float k_nxt = 0.f, q_nxt = 0.f, v_nxt = 0.f, a_nxt = 0.f, g_nxt = 0.f, beta_nxt = 0.f;
        if (t + 1 < NT) {
            size_t idx = ((size_t)(b * NT + t + 1)) * NC + chan;
            k_nxt = kc[idx]; q_nxt = qc[idx]; v_nxt = vc[idx];
            a_nxt = ga[idx]; g_nxt = gg[idx];
            beta_nxt = gbeta[(size_t)(b * NT + t + 1) * NH + h];
        }

        const float4* k4 = reinterpret_cast<const float4*>(sk[buf]);
        const float4* q4 = reinterpret_cast<const float4*>(sq[buf]);

        // Sk = S @ k_t
        float s0 = 0.f, s1 = 0.f, s2 = 0.f, s3 = 0.f;
#pragma unroll
        for (int j = 0; j < NDK / 4; j++) {
            float4 kk = k4[j];
            s0 = fmaf(S[4*j+0], kk.x, s0);
            s1 = fmaf(S[4*j+1], kk.y, s1);
            s2 = fmaf(S[4*j+2], kk.z, s2);
            s3 = fmaf(S[4*j+3], kk.w, s3);
        }
        const float Sk   = (s0 + s1) + (s2 + s3);
        const float coef = beta_cur * (Sk - v_cur);
        const float a    = a_cur;

        // S = a*S - coef*k ;  o = S_new @ q
        float o0 = 0.f, o1 = 0.f, o2 = 0.f, o3 = 0.f;
#pragma unroll
        for (int j = 0; j < NDK / 4; j++) {
            float4 kk = k4[j];
            float4 qq = q4[j];
            S[4*j+0] = fmaf(a, S[4*j+0], -coef * kk.x); o0 = fmaf(S[4*j+0], qq.x, o0);
            S[4*j+1] = fmaf(a, S[4*j+1], -coef * kk.y); o1 = fmaf(S[4*j+1], qq.y, o1);
            S[4*j+2] = fmaf(a, S[4*j+2], -coef * kk.z); o2 = fmaf(S[4*j+2], qq.z, o2);
            S[4*j+3] = fmaf(a, S[4*j+3], -coef * kk.w); o3 = fmaf(S[4*j+3], qq.w, o3);
        }
        float o = (o0 + o1) + (o2 + o3);

        // block LayerNorm over 128 v-channels
        float rs = o, rs2 = o * o;
#pragma unroll
        for (int off = 16; off > 0; off >>= 1) {
            rs  += __shfl_xor_sync(0xffffffffu, rs,  off);
            rs2 += __shfl_xor_sync(0xffffffffu, rs2, off);
        }
        if (lane == 0) { red[wid] = rs; red[4 + wid] = rs2; }
        __syncthreads();
        float mu = (red[0] + red[1] + red[2] + red[3]) * (1.f / 128.f);
        float ms = (red[4] + red[5] + red[6] + red[7]) * (1.f / 128.f);
        float var = ms - mu * mu;
        float y = (o - mu) * rsqrtf(var + 1e-5f) * lg + lb;

        og[((size_t)(b * NT + t)) * NC + chan] = y * g_cur;

        k_cur = k_nxt; q_cur = q_nxt; v_cur = v_nxt;
        a_cur = a_nxt; g_cur = g_nxt; beta_cur = beta_nxt;
    }
}

// ------------------------------------------------------------------
// Launch
// ------------------------------------------------------------------
extern "C" void kernel_launch(void* const* d_in, const int* in_sizes, int n_in,
                              void* d_out, int out_size)
{
    const float* x        = (const float*)d_in[0];
    const float* Wq       = (const float*)d_in[1];
    const float* Wk       = (const float*)d_in[2];
    const float* Wv       = (const float*)d_in[3];
    const float* Wa       = (const float*)d_in[4];
    const float* ba       = (const float*)d_in[5];
    const float* Wb       = (const float*)d_in[6];
    const float* bb       = (const float*)d_in[7];
    const float* conv_q_w = (const float*)d_in[8];
    const float* conv_q_b = (const float*)d_in[9];
    const float* conv_k_w = (const float*)d_in[10];
    const float* conv_k_b = (const float*)d_in[11];
    const float* conv_v_w = (const float*)d_in[12];
    const float* conv_v_b = (const float*)d_in[13];
    const float* Wg       = (const float*)d_in[14];
    const float* ln_g     = (const float*)d_in[15];
    const float* ln_b     = (const float*)d_in[16];
    const float* Wo       = (const float*)d_in[17];
    float* out = (float*)d_out;

    float *q0, *k0, *v0, *qc, *kc, *vc, *pa, *pg, *pbeta, *pog;
    cudaGetSymbolAddress((void**)&q0,   g_q0);
    cudaGetSymbolAddress((void**)&k0,   g_k0);
    cudaGetSymbolAddress((void**)&v0,   g_v0);
    cudaGetSymbolAddress((void**)&qc,   g_qc);
    cudaGetSymbolAddress((void**)&kc,   g_kc);
    cudaGetSymbolAddress((void**)&vc,   g_vc);
    cudaGetSymbolAddress((void**)&pa,   g_a);
    cudaGetSymbolAddress((void**)&pg,   g_gt);
    cudaGetSymbolAddress((void**)&pbeta,g_bt);
    cudaGetSymbolAddress((void**)&pog,  g_og);

    const dim3 blk(256);
    const dim3 grd_full((NC + BN - 1) / BN, (NTOK + BM - 1) / BM);   // 16 x 16
    const dim3 grd_beta((NH + BN - 1) / BN, (NTOK + BM - 1) / BM);   // 1 x 16

    // projections
    gemm_nt<<<grd_full, blk>>>(x, Wq, nullptr, q0,   NTOK, NC, ND, 0);
    gemm_nt<<<grd_full, blk>>>(x, Wk, nullptr, k0,   NTOK, NC, ND, 0);
    gemm_nt<<<grd_full, blk>>>(x, Wv, nullptr, v0,   NTOK, NC, ND, 0);
    gemm_nt<<<grd_full, blk>>>(x, Wa, ba,      pa,   NTOK, NC, ND, 1);
    gemm_nt<<<grd_full, blk>>>(x, Wg, nullptr, pg,   NTOK, NC, ND, 1);
    gemm_nt<<<grd_beta, blk>>>(x, Wb, bb,      pbeta,NTOK, NH, ND, 1);

    // causal depthwise conv + silu (k also gets DK^-0.5)
    const int ctot = NTOK * NC;
    const int cblocks = (ctot + 255) / 256;
    conv_silu<<<cblocks, 256>>>(q0, conv_q_w, conv_q_b, qc, 1.0f);
    conv_silu<<<cblocks, 256>>>(k0, conv_k_w, conv_k_b, kc, 0.08838834764831845f);
    conv_silu<<<cblocks, 256>>>(v0, conv_v_w, conv_v_b, vc, 1.0f);

    // sequential recurrence + LN + gate
    recur_kernel<<<NB * NH, NDK>>>(qc, kc, vc, pa, pbeta, pg, ln_g, ln_b, pog);

    // output projection
    gemm_nt<<<grd_full, blk>>>(pog, Wo, nullptr, out, NTOK, ND, NC, 0);
}

// round 3
// speedup vs baseline: 2.4794x; 2.4794x over previous
#include <cuda_runtime.h>
#include <cuda_bf16.h>
#include <math.h>
#include <stdint.h>

#define NB   2
#define NT   1024
#define ND   2048
#define NH   16
#define NDK  128
#define NTOK (NB*NT)      /* 2048 tokens */
#define NC   (NH*NDK)     /* 2048 channels */
#define KS   (3*ND)       /* 6144: split-precision K (hi|lo|hi) */

// ------------------------------------------------------------------
// Scratch (device globals; no runtime allocation allowed)
// ------------------------------------------------------------------
__device__ __nv_bfloat16 g_xs[(size_t)NTOK*KS];  // split activations
__device__ __nv_bfloat16 g_ws[(size_t)NC*KS];    // split weights (reused per GEMM)
__device__ float g_q0[NTOK*NC];
__device__ float g_k0[NTOK*NC];
__device__ float g_v0[NTOK*NC];
__device__ float g_qc[NTOK*NC];
__device__ float g_kc[NTOK*NC];
__device__ float g_vc[NTOK*NC];
__device__ float g_a [NTOK*NC];
__device__ float g_gt[NTOK*NC];
__device__ float g_or[NTOK*NC];   // raw recurrence output (pre-LN)
__device__ float g_og[NTOK*NC];   // post LN+gate
__device__ float g_bt[NTOK*NH];

// ==================================================================
// Helpers
// ==================================================================
__device__ __forceinline__ uint32_t smem_u32(const void* p) {
    uint32_t r;
    asm("{ .reg .u64 t; cvta.to.shared.u64 t, %1; cvt.u32.u64 %0, t; }"
        : "=r"(r) : "l"(p));
    return r;
}

__device__ __forceinline__ void cp16(uint32_t dst, const void* src) {
    asm volatile("cp.async.cg.shared.global [%0], [%1], 16;\n" :: "r"(dst), "l"(src));
}
__device__ __forceinline__ void cp_commit() {
    asm volatile("cp.async.commit_group;\n" ::: "memory");
}
__device__ __forceinline__ void cp_wait1() {
    asm volatile("cp.async.wait_group 1;\n" ::: "memory");
}
__device__ __forceinline__ void cp_wait0() {
    asm volatile("cp.async.wait_group 0;\n" ::: "memory");
}

__device__ __forceinline__ void ldsm4(uint32_t& r0, uint32_t& r1, uint32_t& r2,
                                      uint32_t& r3, uint32_t addr) {
    asm volatile("ldmatrix.sync.aligned.m8n8.x4.shared.b16 {%0,%1,%2,%3}, [%4];"
                 : "=r"(r0), "=r"(r1), "=r"(r2), "=r"(r3) : "r"(addr));
}

__device__ __forceinline__ void mma16816(float* d, const uint32_t* a,
                                         uint32_t b0, uint32_t b1) {
    asm volatile(
        "mma.sync.aligned.m16n8k16.row.col.f32.bf16.bf16.f32 "
        "{%0,%1,%2,%3}, {%4,%5,%6,%7}, {%8,%9}, {%0,%1,%2,%3};"
        : "+f"(d[0]), "+f"(d[1]), "+f"(d[2]), "+f"(d[3])
        : "r"(a[0]), "r"(a[1]), "r"(a[2]), "r"(a[3]), "r"(b0), "r"(b1));
}

// ==================================================================
// Tensor-core GEMM (HMMA mma.sync): C[m,n] = epi( sum_k A'[m,k] W'[n,k] )
// A': [2048, KS] bf16; W': [2048, KS] bf16 (split-precision K' = 6144)
// 128x128 tile, BK=32, 3-stage cp.async pipeline, 8 warps.
// epi: 0 = store; 1 = sigmoid(acc + bias)
// ==================================================================
#define BK      32
#define STAGES  3
#define KITERS  (KS/BK)      /* 192 */
#define STG_B   16384        /* bytes per stage: A 8KB + B 8KB */

__global__ void __launch_bounds__(256, 2)
tgemm(const __nv_bfloat16* __restrict__ A, const __nv_bfloat16* __restrict__ Bw,
      const float* __restrict__ bias, float* __restrict__ C, int epi)
{
    __shared__ __align__(1024) char smem[STAGES * STG_B];
    const uint32_t sb = smem_u32(smem);

    const int tid  = threadIdx.x;
    const int lane = tid & 31;
    const int wid  = tid >> 5;
    const int wm   = wid & 3;            // 4 warps along m
    const int wn   = wid >> 2;           // 2 warps along n
    const int m0   = blockIdx.y * 128;
    const int n0   = blockIdx.x * 128;

    // ---- load-side addressing: 512 16B chunks per 8KB tile, 2 per thread
    const int r0 = tid >> 2;             // row 0..63
    const int c0 = tid & 3;              // chunk 0..3
    const uint32_t stA0 = r0 * 64 + (((uint32_t)(c0 ^ ((r0 >> 1) & 3))) << 4);
    const uint32_t stA1 = stA0 + 4096;   // row + 64 (same swizzle)

    const __nv_bfloat16* gA0 = A  + (size_t)(m0 + r0)      * KS + c0 * 8;
    const __nv_bfloat16* gA1 = A  + (size_t)(m0 + r0 + 64) * KS + c0 * 8;
    const __nv_bfloat16* gB0 = Bw + (size_t)(n0 + r0)      * KS + c0 * 8;
    const __nv_bfloat16* gB1 = Bw + (size_t)(n0 + r0 + 64) * KS + c0 * 8;

    // ---- mma-side addressing (byte offsets inside a stage)
    const int la = lane & 15, ha = lane >> 4;
    const int arow = wm * 32 + la;
    const uint32_t aswz = (arow >> 1) & 3;
    const uint32_t aoffk0 = arow * 64 + (((uint32_t)((0 + ha) ^ aswz)) << 4);
    const uint32_t aoffk1 = arow * 64 + (((uint32_t)((2 + ha) ^ aswz)) << 4);

    const int brow = wn * 64 + (lane & 7) + ((lane >> 4) & 1) * 8;
    const uint32_t bswz = (brow >> 1) & 3;
    const uint32_t bsel = (lane >> 3) & 1;
    const uint32_t boffk0 = 8192 + brow * 64 + (((uint32_t)((0 + bsel) ^ bswz)) << 4);
    const uint32_t boffk1 = 8192 + brow * 64 + (((uint32_t)((2 + bsel) ^ bswz)) << 4);

    float acc[2][8][4];
#pragma unroll
    for (int mi = 0; mi < 2; mi++)
#pragma unroll
        for (int ni = 0; ni < 8; ni++)
#pragma unroll
            for (int e = 0; e < 4; e++) acc[mi][ni][e] = 0.f;

    // ---- prologue: stages 0 and 1
#pragma unroll
    for (int s = 0; s < STAGES - 1; s++) {
        const uint32_t base = sb + s * STG_B;
        const int kc = s * BK;
        cp16(base + stA0,        gA0 + kc);
        cp16(base + stA1,        gA1 + kc);
        cp16(base + 8192 + stA0, gB0 + kc);
        cp16(base + 8192 + stA1, gB1 + kc);
        cp_commit();
    }

    for (int it = 0; it < KITERS; it++) {
        if (it < KITERS - 1) cp_wait1(); else cp_wait0();
        __syncthreads();

        if (it + 2 < KITERS) {
            const int s = (it + 2) % STAGES;
            const uint32_t base = sb + s * STG_B;
            const int kc = (it + 2) * BK;
            cp16(base + stA0,        gA0 + kc);
            cp16(base + stA1,        gA1 + kc);
            cp16(base + 8192 + stA0, gB0 + kc);
            cp16(base + 8192 + stA1, gB1 + kc);
            cp_commit();
        }

        const uint32_t base = sb + (it % STAGES) * STG_B;

#pragma unroll
        for (int kh = 0; kh < 2; kh++) {
            const uint32_t ao = kh ? aoffk1 : aoffk0;
            const uint32_t bo = kh ? boffk1 : boffk0;

            uint32_t av[2][4];
            ldsm4(av[0][0], av[0][1], av[0][2], av[0][3], base + ao);
            ldsm4(av[1][0], av[1][1], av[1][2], av[1][3], base + ao + 1024);

            uint32_t bv[4][4];
#pragma unroll
            for (int p = 0; p < 4; p++)
                ldsm4(bv[p][0], bv[p][1], bv[p][2], bv[p][3], base + bo + p * 1024);

#pragma unroll
            for (int mi = 0; mi < 2; mi++)
#pragma unroll
                for (int ni = 0; ni < 8; ni++) {
                    const int p = ni >> 1;
                    const int h = (ni & 1) * 2;
                    mma16816(acc[mi][ni], av[mi], bv[p][h], bv[p][h + 1]);
                }
        }
    }

    // ---- epilogue: direct stores (float2, 32B-sector aligned)
    const int g  = lane >> 2;
    const int tg = lane & 3;
#pragma unroll
    for (int mi = 0; mi < 2; mi++) {
        const int row = m0 + wm * 32 + mi * 16 + g;
#pragma unroll
        for (int ni = 0; ni < 8; ni++) {
            const int col = n0 + wn * 64 + ni * 8 + tg * 2;
            float v0 = acc[mi][ni][0], v1 = acc[mi][ni][1];
            float v2 = acc[mi][ni][2], v3 = acc[mi][ni][3];
            if (epi == 1) {
                const float b0 = bias ? bias[col]     : 0.f;
                const float b1 = bias ? bias[col + 1] : 0.f;
                v0 = 1.f / (1.f + expf(-(v0 + b0)));
                v1 = 1.f / (1.f + expf(-(v1 + b1)));
                v2 = 1.f / (1.f + expf(-(v2 + b0)));
                v3 = 1.f / (1.f + expf(-(v3 + b1)));
            }
            *(float2*)(C + (size_t)row * NC + col)       = make_float2(v0, v1);
            *(float2*)(C + (size_t)(row + 8) * NC + col) = make_float2(v2, v3);
        }
    }
}

// ------------------------------------------------------------------
// Split fp32 -> bf16 hi/lo, K-concatenated.
// mode 0 (activation): [hi | lo | hi]   mode 1 (weight): [hi | hi | lo]
// ------------------------------------------------------------------
__global__ void split_mat(const float* __restrict__ in, __nv_bfloat16* __restrict__ out,
                          int total, int mode)
{
    int i = blockIdx.x * blockDim.x + threadIdx.x;
    if (i >= total) return;
    const int r = i >> 11;
    const int k = i & 2047;
    const float a = in[i];
    const __nv_bfloat16 h = __float2bfloat16(a);
    const __nv_bfloat16 l = __float2bfloat16(a - __bfloat162float(h));
    const size_t base = (size_t)r * KS + k;
    out[base] = h;
    if (mode == 0) { out[base + 2048] = l; out[base + 4096] = h; }
    else           { out[base + 2048] = h; out[base + 4096] = l; }
}

// ------------------------------------------------------------------
// beta = sigmoid(x @ Wb^T + bb)
// ------------------------------------------------------------------
__global__ void __launch_bounds__(256)
beta_k(const float* __restrict__ x, const float* __restrict__ Wb,
       const float* __restrict__ bb, float* __restrict__ out)
{
    __shared__ float xs[ND];
    const int row = blockIdx.x;
    for (int i = threadIdx.x; i < ND; i += 256) xs[i] = x[(size_t)row * ND + i];
    __syncthreads();
    const int w = threadIdx.x >> 5, lane = threadIdx.x & 31;
    for (int h = w; h < NH; h += 8) {
        const float* wr = Wb + (size_t)h * ND;
        float s = 0.f;
        for (int i = lane; i < ND; i += 32) s = fmaf(xs[i], wr[i], s);
#pragma unroll
        for (int o = 16; o > 0; o >>= 1) s += __shfl_xor_sync(0xffffffffu, s, o);
        if (lane == 0) out[(size_t)row * NH + h] = 1.f / (1.f + expf(-(s + bb[h])));
    }
}

// ------------------------------------------------------------------
// Causal depthwise conv (K=4) + bias + silu + scale
// ------------------------------------------------------------------
__global__ void conv_silu(const float* __restrict__ in, const float* __restrict__ w,
                          const float* __restrict__ bias, float* __restrict__ out,
                          float scale)
{
    int idx = blockIdx.x * blockDim.x + threadIdx.x;
    if (idx >= NTOK * NC) return;
    const int c  = idx & (NC - 1);
    const int bt = idx >> 11;
    const int t  = bt & (NT - 1);
    const int b  = bt >> 10;

    const float4 wc = *reinterpret_cast<const float4*>(w + c * 4);
    const float* p  = in + ((size_t)b * NT) * NC + c;

    float acc = bias[c];
    if (t >= 3) acc = fmaf(wc.x, p[(size_t)(t - 3) * NC], acc);
    if (t >= 2) acc = fmaf(wc.y, p[(size_t)(t - 2) * NC], acc);
    if (t >= 1) acc = fmaf(wc.z, p[(size_t)(t - 1) * NC], acc);
    acc = fmaf(wc.w, p[(size_t)t * NC], acc);

    out[idx] = (acc / (1.f + expf(-acc))) * scale;
}

// ------------------------------------------------------------------
// Recurrence, v-split 4x: grid = B*H*4 blocks, 128 threads.
// Thread (vloc = tid>>2, kq = tid&3) owns S[vloc][kq*32 .. +31].
// ------------------------------------------------------------------
__global__ void __launch_bounds__(128)
recur2(const float* __restrict__ qc, const float* __restrict__ kc,
       const float* __restrict__ vc, const float* __restrict__ ga,
       const float* __restrict__ gbeta, float* __restrict__ o_raw)
{
    const int bid  = blockIdx.x;
    const int b    = bid >> 6;
    const int h    = (bid >> 2) & 15;
    const int vblk = bid & 3;
    const int tid  = threadIdx.x;
    const int vloc = tid >> 2;
    const int kq   = tid & 3;

    __shared__ __align__(16) float sk[2][160];
    __shared__ __align__(16) float sq[2][160];

    float S[32];
#pragma unroll
    for (int j = 0; j < 32; j++) S[j] = 0.f;

    const int kchan = h * NDK + tid;
    const int vchan = h * NDK + vblk * 32 + vloc;
    const int sidx  = (tid >> 5) * 40 + (tid & 31);
    const size_t tok0 = (size_t)b * NT;

    float k_cur = kc[tok0 * NC + kchan];
    float q_cur = qc[tok0 * NC + kchan];
    float v_cur = vc[tok0 * NC + vchan];
    float a_cur = ga[tok0 * NC + vchan];
    float be_cur = gbeta[tok0 * NH + h];

    for (int t = 0; t < NT; t++) {
        const int buf = t & 1;
        sk[buf][sidx] = k_cur;
        sq[buf][sidx] = q_cur;
        __syncthreads();

        float k_n = 0.f, q_n = 0.f, v_n = 0.f, a_n = 0.f, be_n = 0.f;
        if (t + 1 < NT) {
            const size_t idx = (tok0 + t + 1) * NC;
            k_n = kc[idx + kchan]; q_n = qc[idx + kchan];
            v_n = vc[idx + vchan]; a_n = ga[idx + vchan];
            be_n = gbeta[(tok0 + t + 1) * NH + h];
        }

        const float4* kb = (const float4*)&sk[buf][kq * 40];
        const float4* qb = (const float4*)&sq[buf][kq * 40];

        float s0 = 0.f, s1 = 0.f, s2 = 0.f, s3 = 0.f;
#pragma unroll
        for (int j = 0; j < 8; j++) {
            const float4 kk = kb[j];
            s0 = fmaf(S[4*j+0], kk.x, s0);
            s1 = fmaf(S[4*j+1], kk.y, s1);
            s2 = fmaf(S[4*j+2], kk.z, s2);
            s3 = fmaf(S[4*j+3], kk.w, s3);
        }
        float Sk = (s0 + s1) + (s2 + s3);
        Sk += __shfl_xor_sync(0xffffffffu, Sk, 1);
        Sk += __shfl_xor_sync(0xffffffffu, Sk, 2);

        const float coef = be_cur * (Sk - v_cur);
        const float a = a_cur;

        float o0 = 0.f, o1 = 0.f, o2 = 0.f, o3 = 0.f;
#pragma unroll
        for (int j = 0; j < 8; j++) {
            const float4 kk = kb[j];
            const float4 qq = qb[j];
            S[4*j+0] = fmaf(a, S[4*j+0], -coef * kk.x); o0 = fmaf(S[4*j+0], qq.x, o0);
            S[4*j+1] = fmaf(a, S[4*j+1], -coef * kk.y); o1 = fmaf(S[4*j+1], qq.y, o1);
            S[4*j+2] = fmaf(a, S[4*j+2], -coef * kk.z); o2 = fmaf(S[4*j+2], qq.z, o2);
            S[4*j+3] = fmaf(a, S[4*j+3], -coef * kk.w); o3 = fmaf(S[4*j+3], qq.w, o3);
        }
        float o = (o0 + o1) + (o2 + o3);
        o += __shfl_xor_sync(0xffffffffu, o, 1);
        o += __shfl_xor_sync(0xffffffffu, o, 2);
        if (kq == 0) o_raw[(tok0 + t) * NC + vchan] = o;

        k_cur = k_n; q_cur = q_n; v_cur = v_n; a_cur = a_n; be_cur = be_n;
    }
}

// ------------------------------------------------------------------
// LayerNorm over DV=128 + gate.  grid = NTOK*NH, block = 128
// ------------------------------------------------------------------
__global__ void __launch_bounds__(128)
ln_gate(const float* __restrict__ o_raw, const float* __restrict__ gg,
        const float* __restrict__ ln_g, const float* __restrict__ ln_b,
        float* __restrict__ og)
{
    const int bid = blockIdx.x;
    const int tok = bid >> 4, h = bid & 15;
    const int v = threadIdx.x, lane = v & 31, wid = v >> 5;
    const size_t idx = (size_t)tok * NC + h * NDK + v;
    const float o = o_raw[idx];

    __shared__ float red[8];
    float rs = o, rs2 = o * o;
#pragma unroll
    for (int off = 16; off > 0; off >>= 1) {
        rs  += __shfl_xor_sync(0xffffffffu, rs,  off);
        rs2 += __shfl_xor_sync(0xffffffffu, rs2, off);
    }
    if (lane == 0) { red[wid] = rs; red[4 + wid] = rs2; }
    __syncthreads();
    const float mu  = (red[0] + red[1] + red[2] + red[3]) * (1.f / 128.f);
    const float ms  = (red[4] + red[5] + red[6] + red[7]) * (1.f / 128.f);
    const float var = ms - mu * mu;
    const float y = (o - mu) * rsqrtf(var + 1e-5f) * ln_g[v] + ln_b[v];
    og[idx] = y * gg[idx];
}

// ------------------------------------------------------------------
// Launch
// ------------------------------------------------------------------
extern "C" void kernel_launch(void* const* d_in, const int* in_sizes, int n_in,
                              void* d_out, int out_size)
{
    const float* x        = (const float*)d_in[0];
    const float* Wq       = (const float*)d_in[1];
    const float* Wk       = (const float*)d_in[2];
    const float* Wv       = (const float*)d_in[3];
    const float* Wa       = (const float*)d_in[4];
    const float* ba       = (const float*)d_in[5];
    const float* Wb       = (const float*)d_in[6];
    const float* bb       = (const float*)d_in[7];
    const float* conv_q_w = (const float*)d_in[8];
    const float* conv_q_b = (const float*)d_in[9];
    const float* conv_k_w = (const float*)d_in[10];
    const float* conv_k_b = (const float*)d_in[11];
    const float* conv_v_w = (const float*)d_in[12];
    const float* conv_v_b = (const float*)d_in[13];
    const float* Wg       = (const float*)d_in[14];
    const float* ln_g     = (const float*)d_in[15];
    const float* ln_b     = (const float*)d_in[16];
    const float* Wo       = (const float*)d_in[17];
    float* out = (float*)d_out;

    __nv_bfloat16 *xs, *ws;
    float *q0, *k0, *v0, *qc, *kc, *vc, *pa, *pg, *praw, *pog, *pbeta;
    cudaGetSymbolAddress((void**)&xs,    g_xs);
    cudaGetSymbolAddress((void**)&ws,    g_ws);
    cudaGetSymbolAddress((void**)&q0,    g_q0);
    cudaGetSymbolAddress((void**)&k0,    g_k0);
    cudaGetSymbolAddress((void**)&v0,    g_v0);
    cudaGetSymbolAddress((void**)&qc,    g_qc);
    cudaGetSymbolAddress((void**)&kc,    g_kc);
    cudaGetSymbolAddress((void**)&vc,    g_vc);
    cudaGetSymbolAddress((void**)&pa,    g_a);
    cudaGetSymbolAddress((void**)&pg,    g_gt);
    cudaGetSymbolAddress((void**)&praw,  g_or);
    cudaGetSymbolAddress((void**)&pog,   g_og);
    cudaGetSymbolAddress((void**)&pbeta, g_bt);

    const int tot = NTOK * ND;
    const int sblk = (tot + 255) / 256;
    const dim3 tg_grid(16, 16);

    // split x once; beta from fp32 x
    split_mat<<<sblk, 256>>>(x, xs, tot, 0);
    beta_k<<<NTOK, 256>>>(x, Wb, bb, pbeta);

    // 5 input projections on tensor cores (weight split buffer reused serially)
    split_mat<<<sblk, 256>>>(Wq, ws, tot, 1);
    tgemm<<<tg_grid, 256>>>(xs, ws, nullptr, q0, 0);
    split_mat<<<sblk, 256>>>(Wk, ws, tot, 1);
    tgemm<<<tg_grid, 256>>>(xs, ws, nullptr, k0, 0);
    split_mat<<<sblk, 256>>>(Wv, ws, tot, 1);
    tgemm<<<tg_grid, 256>>>(xs, ws, nullptr, v0, 0);
    split_mat<<<sblk, 256>>>(Wa, ws, tot, 1);
    tgemm<<<tg_grid, 256>>>(xs, ws, ba, pa, 1);
    split_mat<<<sblk, 256>>>(Wg, ws, tot, 1);
    tgemm<<<tg_grid, 256>>>(xs, ws, nullptr, pg, 1);

    // conv + silu
    const int cblocks = (NTOK * NC + 255) / 256;
    conv_silu<<<cblocks, 256>>>(q0, conv_q_w, conv_q_b, qc, 1.0f);
    conv_silu<<<cblocks, 256>>>(k0, conv_k_w, conv_k_b, kc, 0.08838834764831845f);
    conv_silu<<<cblocks, 256>>>(v0, conv_v_w, conv_v_b, vc, 1.0f);

    // recurrence (v-split 4x) then LN + gate
    recur2<<<NB * NH * 4, 128>>>(qc, kc, vc, pa, pbeta, praw);
    ln_gate<<<NTOK * NH, 128>>>(praw, pg, ln_g, ln_b, pog);

    // output projection
    split_mat<<<sblk, 256>>>(pog, xs, tot, 0);
    split_mat<<<sblk, 256>>>(Wo, ws, tot, 1);
    tgemm<<<tg_grid, 256>>>(xs, ws, nullptr, out, 0);
}

// round 4
// speedup vs baseline: 2.6245x; 1.0585x over previous
#include <cuda_runtime.h>
#include <cuda_bf16.h>
#include <math.h>
#include <stdint.h>

#define NB   2
#define NT   1024
#define ND   2048
#define NH   16
#define NDK  128
#define NTOK (NB*NT)      /* 2048 tokens */
#define NC   (NH*NDK)     /* 2048 channels */
#define KS   (3*ND)       /* 6144: split-precision K (hi|lo|hi) */
#define WSTRIDE ((size_t)NC*KS)

// ------------------------------------------------------------------
// Scratch (device globals; no runtime allocation allowed)
// ------------------------------------------------------------------
__device__ __nv_bfloat16 g_xs[(size_t)NTOK*KS];   // split activations
__device__ __nv_bfloat16 g_ws[6*WSTRIDE];         // 6 split weights (q,k,v,a,g,o)
__device__ float g_q0[NTOK*NC];
__device__ float g_k0[NTOK*NC];
__device__ float g_v0[NTOK*NC];
__device__ float g_qc[NTOK*NC];
__device__ float g_kc[NTOK*NC];
__device__ float g_vc[NTOK*NC];
__device__ float g_a [NTOK*NC];
__device__ float g_gt[NTOK*NC];
__device__ float g_o4[(size_t)NTOK*NC*4];         // partial recurrence outputs
__device__ float g_og[NTOK*NC];                   // post LN+gate
__device__ float g_bt[NTOK*NH];

// ==================================================================
// Helpers
// ==================================================================
__device__ __forceinline__ uint32_t smem_u32(const void* p) {
    uint32_t r;
    asm("{ .reg .u64 t; cvta.to.shared.u64 t, %1; cvt.u32.u64 %0, t; }"
        : "=r"(r) : "l"(p));
    return r;
}
__device__ __forceinline__ void cp16(uint32_t dst, const void* src) {
    asm volatile("cp.async.cg.shared.global [%0], [%1], 16;\n" :: "r"(dst), "l"(src));
}
__device__ __forceinline__ void cp_commit() {
    asm volatile("cp.async.commit_group;\n" ::: "memory");
}
__device__ __forceinline__ void cp_wait2() {
    asm volatile("cp.async.wait_group 2;\n" ::: "memory");
}
__device__ __forceinline__ void ldsm4(uint32_t& r0, uint32_t& r1, uint32_t& r2,
                                      uint32_t& r3, uint32_t addr) {
    asm volatile("ldmatrix.sync.aligned.m8n8.x4.shared.b16 {%0,%1,%2,%3}, [%4];"
                 : "=r"(r0), "=r"(r1), "=r"(r2), "=r"(r3) : "r"(addr));
}
__device__ __forceinline__ void mma16816(float* d, const uint32_t* a,
                                         uint32_t b0, uint32_t b1) {
    asm volatile(
        "mma.sync.aligned.m16n8k16.row.col.f32.bf16.bf16.f32 "
        "{%0,%1,%2,%3}, {%4,%5,%6,%7}, {%8,%9}, {%0,%1,%2,%3};"
        : "+f"(d[0]), "+f"(d[1]), "+f"(d[2]), "+f"(d[3])
        : "r"(a[0]), "r"(a[1]), "r"(a[2]), "r"(a[3]), "r"(b0), "r"(b1));
}
__device__ __forceinline__ float fsig(float z) {
    return 1.f / (1.f + __expf(-z));
}

// ==================================================================
// Tensor-core GEMM (HMMA mma.sync): C[m,n] = epi( sum_k A'[m,k] W'[n,k] )
// 128x128 tile, BK=32, 4-stage cp.async pipeline (dynamic smem), 8 warps.
// ==================================================================
#define BK      32
#define STAGES  4
#define KITERS  (KS/BK)      /* 192 */
#define STG_B   16384        /* bytes per stage: A 8KB + B 8KB */
#define TG_SMEM (STAGES*STG_B)

__global__ void __launch_bounds__(256, 2)
tgemm(const __nv_bfloat16* __restrict__ A, const __nv_bfloat16* __restrict__ Bw,
      const float* __restrict__ bias, float* __restrict__ C, int epi)
{
    extern __shared__ __align__(1024) char smem[];
    const uint32_t sb = smem_u32(smem);

    const int tid  = threadIdx.x;
    const int lane = tid & 31;
    const int wid  = tid >> 5;
    const int wm   = wid & 3;            // 4 warps along m
    const int wn   = wid >> 2;           // 2 warps along n
    const int m0   = blockIdx.y * 128;
    const int n0   = blockIdx.x * 128;

    // ---- load-side addressing
    const int r0 = tid >> 2;             // row 0..63
    const int c0 = tid & 3;              // 16B chunk 0..3
    const uint32_t stA0 = r0 * 64 + (((uint32_t)(c0 ^ ((r0 >> 1) & 3))) << 4);
    const uint32_t stA1 = stA0 + 4096;

    const __nv_bfloat16* gA0 = A  + (size_t)(m0 + r0)      * KS + c0 * 8;
    const __nv_bfloat16* gA1 = A  + (size_t)(m0 + r0 + 64) * KS + c0 * 8;
    const __nv_bfloat16* gB0 = Bw + (size_t)(n0 + r0)      * KS + c0 * 8;
    const __nv_bfloat16* gB1 = Bw + (size_t)(n0 + r0 + 64) * KS + c0 * 8;

    // ---- mma-side addressing (byte offsets inside a stage)
    const int la = lane & 15, ha = lane >> 4;
    const int arow = wm * 32 + la;
    const uint32_t aswz = (arow >> 1) & 3;
    const uint32_t aoffk0 = arow * 64 + (((uint32_t)((0 + ha) ^ aswz)) << 4);
    const uint32_t aoffk1 = arow * 64 + (((uint32_t)((2 + ha) ^ aswz)) << 4);

    const int brow = wn * 64 + (lane & 7) + ((lane >> 4) & 1) * 8;
    const uint32_t bswz = (brow >> 1) & 3;
    const uint32_t bsel = (lane >> 3) & 1;
    const uint32_t boffk0 = 8192 + brow * 64 + (((uint32_t)((0 + bsel) ^ bswz)) << 4);
    const uint32_t boffk1 = 8192 + brow * 64 + (((uint32_t)((2 + bsel) ^ bswz)) << 4);

    float acc[2][8][4];
#pragma unroll
    for (int mi = 0; mi < 2; mi++)
#pragma unroll
        for (int ni = 0; ni < 8; ni++)
#pragma unroll
            for (int e = 0; e < 4; e++) acc[mi][ni][e] = 0.f;

    // ---- prologue: stages 0..2
#pragma unroll
    for (int s = 0; s < STAGES - 1; s++) {
        const uint32_t base = sb + s * STG_B;
        const int kc = s * BK;
        cp16(base + stA0,        gA0 + kc);
        cp16(base + stA1,        gA1 + kc);
        cp16(base + 8192 + stA0, gB0 + kc);
        cp16(base + 8192 + stA1, gB1 + kc);
        cp_commit();
    }

    for (int it = 0; it < KITERS; it++) {
        cp_wait2();          // group 'it' complete
        __syncthreads();     // visibility + buffer (it-1)%4 free for overwrite

        if (it + 3 < KITERS) {
            const uint32_t base = sb + ((it + 3) & 3) * STG_B;
            const int kc = (it + 3) * BK;
            cp16(base + stA0,        gA0 + kc);
            cp16(base + stA1,        gA1 + kc);
            cp16(base + 8192 + stA0, gB0 + kc);
            cp16(base + 8192 + stA1, gB1 + kc);
        }
        cp_commit();         // commit (possibly empty) to keep group count

        const uint32_t base = sb + (it & 3) * STG_B;

#pragma unroll
        for (int kh = 0; kh < 2; kh++) {
            const uint32_t ao = kh ? aoffk1 : aoffk0;
            const uint32_t bo = kh ? boffk1 : boffk0;

            uint32_t av[2][4];
            ldsm4(av[0][0], av[0][1], av[0][2], av[0][3], base + ao);
            ldsm4(av[1][0], av[1][1], av[1][2], av[1][3], base + ao + 1024);

            uint32_t bv[4][4];
#pragma unroll
            for (int p = 0; p < 4; p++)
                ldsm4(bv[p][0], bv[p][1], bv[p][2], bv[p][3], base + bo + p * 1024);

#pragma unroll
            for (int mi = 0; mi < 2; mi++)
#pragma unroll
                for (int ni = 0; ni < 8; ni++) {
                    const int p = ni >> 1;
                    const int h = (ni & 1) * 2;
                    mma16816(acc[mi][ni], av[mi], bv[p][h], bv[p][h + 1]);
                }
        }
    }

    // ---- epilogue
    const int g  = lane >> 2;
    const int tg = lane & 3;
#pragma unroll
    for (int mi = 0; mi < 2; mi++) {
        const int row = m0 + wm * 32 + mi * 16 + g;
#pragma unroll
        for (int ni = 0; ni < 8; ni++) {
            const int col = n0 + wn * 64 + ni * 8 + tg * 2;
            float v0 = acc[mi][ni][0], v1 = acc[mi][ni][1];
            float v2 = acc[mi][ni][2], v3 = acc[mi][ni][3];
            if (epi == 1) {
                const float b0 = bias ? bias[col]     : 0.f;
                const float b1 = bias ? bias[col + 1] : 0.f;
                v0 = fsig(v0 + b0); v1 = fsig(v1 + b1);
                v2 = fsig(v2 + b0); v3 = fsig(v3 + b1);
            }
            *(float2*)(C + (size_t)row * NC + col)       = make_float2(v0, v1);
            *(float2*)(C + (size_t)(row + 8) * NC + col) = make_float2(v2, v3);
        }
    }
}

// ------------------------------------------------------------------
// Split fp32 -> bf16 hi/lo, K-concatenated (float4 vectorized).
// mode 0 (activation): [hi | lo | hi]   mode 1 (weight): [hi | hi | lo]
// ------------------------------------------------------------------
__device__ __forceinline__ void split_body(const float* __restrict__ in,
                                           __nv_bfloat16* __restrict__ out,
                                           int mode, int i /* float4 index */)
{
    const int r  = i >> 9;               // (i*4) / 2048
    const int k4 = (i << 2) & 2047;
    const float4 a = ((const float4*)in)[i];

    __nv_bfloat162 h01 = __floats2bfloat162_rn(a.x, a.y);
    __nv_bfloat162 h23 = __floats2bfloat162_rn(a.z, a.w);
    const float lx = a.x - __bfloat162float(__low2bfloat16(h01));
    const float ly = a.y - __bfloat162float(__high2bfloat16(h01));
    const float lz = a.z - __bfloat162float(__low2bfloat16(h23));
    const float lw = a.w - __bfloat162float(__high2bfloat16(h23));
    __nv_bfloat162 l01 = __floats2bfloat162_rn(lx, ly);
    __nv_bfloat162 l23 = __floats2bfloat162_rn(lz, lw);

    uint2 hp, lp;
    hp.x = *(const uint32_t*)&h01; hp.y = *(const uint32_t*)&h23;
    lp.x = *(const uint32_t*)&l01; lp.y = *(const uint32_t*)&l23;

    __nv_bfloat16* base = out + (size_t)r * KS + k4;
    *(uint2*)(base) = hp;
    if (mode == 0) { *(uint2*)(base + 2048) = lp; *(uint2*)(base + 4096) = hp; }
    else           { *(uint2*)(base + 2048) = hp; *(uint2*)(base + 4096) = lp; }
}

// One launch: which = blockIdx.y: 0 = x (mode 0), 1..6 = weights (mode 1)
__global__ void __launch_bounds__(256)
split_all(const float* __restrict__ x,  const float* __restrict__ Wq,
          const float* __restrict__ Wk, const float* __restrict__ Wv,
          const float* __restrict__ Wa, const float* __restrict__ Wg,
          const float* __restrict__ Wo,
          __nv_bfloat16* __restrict__ xs, __nv_bfloat16* __restrict__ ws)
{
    const int i = blockIdx.x * 256 + threadIdx.x;
    if (i >= (NTOK * ND) / 4) return;
    const int which = blockIdx.y;
    if (which == 0)      split_body(x,  xs, 0, i);
    else if (which == 1) split_body(Wq, ws + 0 * WSTRIDE, 1, i);
    else if (which == 2) split_body(Wk, ws + 1 * WSTRIDE, 1, i);
    else if (which == 3) split_body(Wv, ws + 2 * WSTRIDE, 1, i);
    else if (which == 4) split_body(Wa, ws + 3 * WSTRIDE, 1, i);
    else if (which == 5) split_body(Wg, ws + 4 * WSTRIDE, 1, i);
    else                 split_body(Wo, ws + 5 * WSTRIDE, 1, i);
}

__global__ void __launch_bounds__(256)
split4(const float* __restrict__ in, __nv_bfloat16* __restrict__ out, int mode)
{
    const int i = blockIdx.x * 256 + threadIdx.x;
    if (i >= (NTOK * ND) / 4) return;
    split_body(in, out, mode, i);
}

// ------------------------------------------------------------------
// beta = sigmoid(x @ Wb^T + bb)
// ------------------------------------------------------------------
__global__ void __launch_bounds__(256)
beta_k(const float* __restrict__ x, const float* __restrict__ Wb,
       const float* __restrict__ bb, float* __restrict__ out)
{
    __shared__ float xs[ND];
    const int row = blockIdx.x;
    for (int i = threadIdx.x; i < ND; i += 256) xs[i] = x[(size_t)row * ND + i];
    __syncthreads();
    const int w = threadIdx.x >> 5, lane = threadIdx.x & 31;
    for (int h = w; h < NH; h += 8) {
        const float* wr = Wb + (size_t)h * ND;
        float s = 0.f;
        for (int i = lane; i < ND; i += 32) s = fmaf(xs[i], wr[i], s);
#pragma unroll
        for (int o = 16; o > 0; o >>= 1) s += __shfl_xor_sync(0xffffffffu, s, o);
        if (lane == 0) out[(size_t)row * NH + h] = fsig(s + bb[h]);
    }
}

// ------------------------------------------------------------------
// Fused causal depthwise conv (K=4) + bias + silu + scale, float4, q/k/v
// blockIdx.y selects stream: 0=q, 1=k (scaled), 2=v
// ------------------------------------------------------------------
__global__ void __launch_bounds__(256)
conv3(const float* __restrict__ q0, const float* __restrict__ k0,
      const float* __restrict__ v0,
      const float* __restrict__ wq, const float* __restrict__ wk,
      const float* __restrict__ wv,
      const float* __restrict__ bq, const float* __restrict__ bk,
      const float* __restrict__ bv,
      float* __restrict__ qc, float* __restrict__ kc, float* __restrict__ vc)
{
    const int i = blockIdx.x * 256 + threadIdx.x;
    if (i >= (NTOK * NC) / 4) return;

    const float* in; const float* w; const float* bias; float* out; float scale;
    if (blockIdx.y == 0)      { in = q0; w = wq; bias = bq; out = qc; scale = 1.f; }
    else if (blockIdx.y == 1) { in = k0; w = wk; bias = bk; out = kc; scale = 0.08838834764831845f; }
    else                      { in = v0; w = wv; bias = bv; out = vc; scale = 1.f; }

    const int c  = (i << 2) & (NC - 1);
    const int bt = (i << 2) >> 11;
    const int t  = bt & (NT - 1);

    const float4 w0 = ((const float4*)w)[c + 0];
    const float4 w1 = ((const float4*)w)[c + 1];
    const float4 w2 = ((const float4*)w)[c + 2];
    const float4 w3 = ((const float4*)w)[c + 3];
    const float* p = in + (size_t)bt * NC + c;

    float4 acc = *(const float4*)(bias + c);
    float4 xv = *(const float4*)p;
    acc.x = fmaf(w0.w, xv.x, acc.x); acc.y = fmaf(w1.w, xv.y, acc.y);
    acc.z = fmaf(w2.w, xv.z, acc.z); acc.w = fmaf(w3.w, xv.w, acc.w);
    if (t >= 1) {
        xv = *(const float4*)(p - NC);
        acc.x = fmaf(w0.z, xv.x, acc.x); acc.y = fmaf(w1.z, xv.y, acc.y);
        acc.z = fmaf(w2.z, xv.z, acc.z); acc.w = fmaf(w3.z, xv.w, acc.w);
    }
    if (t >= 2) {
        xv = *(const float4*)(p - 2 * NC);
        acc.x = fmaf(w0.y, xv.x, acc.x); acc.y = fmaf(w1.y, xv.y, acc.y);
        acc.z = fmaf(w2.y, xv.z, acc.z); acc.w = fmaf(w3.y, xv.w, acc.w);
    }
    if (t >= 3) {
        xv = *(const float4*)(p - 3 * NC);
        acc.x = fmaf(w0.x, xv.x, acc.x); acc.y = fmaf(w1.x, xv.y, acc.y);
        acc.z = fmaf(w2.x, xv.z, acc.z); acc.w = fmaf(w3.x, xv.w, acc.w);
    }
    float4 r;
    r.x = acc.x * fsig(acc.x) * scale;
    r.y = acc.y * fsig(acc.y) * scale;
    r.z = acc.z * fsig(acc.z) * scale;
    r.w = acc.w * fsig(acc.w) * scale;
    *(float4*)(out + (size_t)bt * NC + c) = r;
}

// ------------------------------------------------------------------
// Recurrence, v-split 4x, deferred o-reduction.
// Thread (vloc = tid>>2, kq = tid&3) owns S[vloc][kq*32 .. +31].
// Stores per-thread partial o to o4; ln_gate sums the 4 partials.
// ------------------------------------------------------------------
__global__ void __launch_bounds__(128)
recur2(const float* __restrict__ qc, const float* __restrict__ kc,
       const float* __restrict__ vc, const float* __restrict__ ga,
       const float* __restrict__ gbeta, float* __restrict__ o4)
{
    const int bid  = blockIdx.x;
    const int b    = bid >> 6;
    const int h    = (bid >> 2) & 15;
    const int vblk = bid & 3;
    const int tid  = threadIdx.x;
    const int vloc = tid >> 2;
    const int kq   = tid & 3;

    __shared__ __align__(16) float sk[2][160];
    __shared__ __align__(16) float sq[2][160];

    float S[32];
#pragma unroll
    for (int j = 0; j < 32; j++) S[j] = 0.f;

    const int kchan = h * NDK + tid;
    const int vchan = h * NDK + vblk * 32 + vloc;
    const int sidx  = (tid >> 5) * 40 + (tid & 31);
    const size_t tok0 = (size_t)b * NT;

    float k_cur = kc[tok0 * NC + kchan];
    float q_cur = qc[tok0 * NC + kchan];
    float v_cur = vc[tok0 * NC + vchan];
    float a_cur = ga[tok0 * NC + vchan];
    float be_cur = gbeta[tok0 * NH + h];

    for (int t = 0; t < NT; t++) {
        const int buf = t & 1;
        sk[buf][sidx] = k_cur;
        sq[buf][sidx] = q_cur;
        __syncthreads();

        float k_n = 0.f, q_n = 0.f, v_n = 0.f, a_n = 0.f, be_n = 0.f;
        if (t + 1 < NT) {
            const size_t idx = (tok0 + t + 1) * NC;
            k_n = kc[idx + kchan]; q_n = qc[idx + kchan];
            v_n = vc[idx + vchan]; a_n = ga[idx + vchan];
            be_n = gbeta[(tok0 + t + 1) * NH + h];
        }

        const float4* kb = (const float4*)&sk[buf][kq * 40];
        const float4* qb = (const float4*)&sq[buf][kq * 40];

        float p0 = 0.f, p1 = 0.f, p2 = 0.f, p3 = 0.f;
        float p4 = 0.f, p5 = 0.f, p6 = 0.f, p7 = 0.f;
#pragma unroll
        for (int j = 0; j < 4; j++) {
            const float4 ka = kb[2 * j];
            const float4 kc2 = kb[2 * j + 1];
            p0 = fmaf(S[8*j+0], ka.x,  p0);
            p1 = fmaf(S[8*j+1], ka.y,  p1);
            p2 = fmaf(S[8*j+2], ka.z,  p2);
            p3 = fmaf(S[8*j+3], ka.w,  p3);
            p4 = fmaf(S[8*j+4], kc2.x, p4);
            p5 = fmaf(S[8*j+5], kc2.y, p5);
            p6 = fmaf(S[8*j+6], kc2.z, p6);
            p7 = fmaf(S[8*j+7], kc2.w, p7);
        }
        float Sk = ((p0 + p1) + (p2 + p3)) + ((p4 + p5) + (p6 + p7));
        Sk += __shfl_xor_sync(0xffffffffu, Sk, 1);
        Sk += __shfl_xor_sync(0xffffffffu, Sk, 2);

        const float coef = be_cur * (Sk - v_cur);
        const float a = a_cur;

        float o0 = 0.f, o1 = 0.f, o2 = 0.f, o3 = 0.f;
        float o4r = 0.f, o5 = 0.f, o6 = 0.f, o7 = 0.f;
#pragma unroll
        for (int j = 0; j < 4; j++) {
            const float4 ka  = kb[2 * j];
            const float4 kc2 = kb[2 * j + 1];
            const float4 qa  = qb[2 * j];
            const float4 qc2 = qb[2 * j + 1];
            S[8*j+0] = fmaf(a, S[8*j+0], -coef * ka.x);  o0  = fmaf(S[8*j+0], qa.x,  o0);
            S[8*j+1] = fmaf(a, S[8*j+1], -coef * ka.y);  o1  = fmaf(S[8*j+1], qa.y,  o1);
            S[8*j+2] = fmaf(a, S[8*j+2], -coef * ka.z);  o2  = fmaf(S[8*j+2], qa.z,  o2);
            S[8*j+3] = fmaf(a, S[8*j+3], -coef * ka.w);  o3  = fmaf(S[8*j+3], qa.w,  o3);
            S[8*j+4] = fmaf(a, S[8*j+4], -coef * kc2.x); o4r = fmaf(S[8*j+4], qc2.x, o4r);
            S[8*j+5] = fmaf(a, S[8*j+5], -coef * kc2.y); o5  = fmaf(S[8*j+5], qc2.y, o5);
            S[8*j+6] = fmaf(a, S[8*j+6], -coef * kc2.z); o6  = fmaf(S[8*j+6], qc2.z, o6);
            S[8*j+7] = fmaf(a, S[8*j+7], -coef * kc2.w); o7  = fmaf(S[8*j+7], qc2.w, o7);
        }
        const float op = ((o0 + o1) + (o2 + o3)) + ((o4r + o5) + (o6 + o7));
        o4[((tok0 + t) * NC + vchan) * 4 + kq] = op;   // per-thread partial

        k_cur = k_n; q_cur = q_n; v_cur = v_n; a_cur = a_n; be_cur = be_n;
    }
}

// ------------------------------------------------------------------
// Sum 4 partials + LayerNorm over DV=128 + gate.  grid = NTOK*NH
// ------------------------------------------------------------------
__global__ void __launch_bounds__(128)
ln_gate(const float* __restrict__ o4, const float* __restrict__ gg,
        const float* __restrict__ ln_g, const float* __restrict__ ln_b,
        float* __restrict__ og)
{
    const int bid = blockIdx.x;
    const int tok = bid >> 4, h = bid & 15;
    const int v = threadIdx.x, lane = v & 31, wid = v >> 5;
    const size_t idx = (size_t)tok * NC + h * NDK + v;

    const float4 part = ((const float4*)o4)[idx];
    const float o = (part.x + part.y) + (part.z + part.w);

    __shared__ float red[8];
    float rs = o, rs2 = o * o;
#pragma unroll
    for (int off = 16; off > 0; off >>= 1) {
        rs  += __shfl_xor_sync(0xffffffffu, rs,  off);
        rs2 += __shfl_xor_sync(0xffffffffu, rs2, off);
    }
    if (lane == 0) { red[wid] = rs; red[4 + wid] = rs2; }
    __syncthreads();
    const float mu  = (red[0] + red[1] + red[2] + red[3]) * (1.f / 128.f);
    const float ms  = (red[4] + red[5] + red[6] + red[7]) * (1.f / 128.f);
    const float var = ms - mu * mu;
    const float y = (o - mu) * rsqrtf(var + 1e-5f) * ln_g[v] + ln_b[v];
    og[idx] = y * gg[idx];
}

// ------------------------------------------------------------------
// Launch
// ------------------------------------------------------------------
extern "C" void kernel_launch(void* const* d_in, const int* in_sizes, int n_in,
                              void* d_out, int out_size)
{
    const float* x        = (const float*)d_in[0];
    const float* Wq       = (const float*)d_in[1];
    const float* Wk       = (const float*)d_in[2];
    const float* Wv       = (const float*)d_in[3];
    const float* Wa       = (const float*)d_in[4];
    const float* ba       = (const float*)d_in[5];
    const float* Wb       = (const float*)d_in[6];
    const float* bb       = (const float*)d_in[7];
    const float* conv_q_w = (const float*)d_in[8];
    const float* conv_q_b = (const float*)d_in[9];
    const float* conv_k_w = (const float*)d_in[10];
    const float* conv_k_b = (const float*)d_in[11];
    const float* conv_v_w = (const float*)d_in[12];
    const float* conv_v_b = (const float*)d_in[13];
    const float* Wg       = (const float*)d_in[14];
    const float* ln_g     = (const float*)d_in[15];
    const float* ln_b     = (const float*)d_in[16];
    const float* Wo       = (const float*)d_in[17];
    float* out = (float*)d_out;

    __nv_bfloat16 *xs, *ws;
    float *q0, *k0, *v0, *qc, *kc, *vc, *pa, *pg, *po4, *pog, *pbeta;
    cudaGetSymbolAddress((void**)&xs,    g_xs);
    cudaGetSymbolAddress((void**)&ws,    g_ws);
    cudaGetSymbolAddress((void**)&q0,    g_q0);
    cudaGetSymbolAddress((void**)&k0,    g_k0);
    cudaGetSymbolAddress((void**)&v0,    g_v0);
    cudaGetSymbolAddress((void**)&qc,    g_qc);
    cudaGetSymbolAddress((void**)&kc,    g_kc);
    cudaGetSymbolAddress((void**)&vc,    g_vc);
    cudaGetSymbolAddress((void**)&pa,    g_a);
    cudaGetSymbolAddress((void**)&pg,    g_gt);
    cudaGetSymbolAddress((void**)&po4,   g_o4);
    cudaGetSymbolAddress((void**)&pog,   g_og);
    cudaGetSymbolAddress((void**)&pbeta, g_bt);

    static bool attr_set = false;
    if (!attr_set) {
        cudaFuncSetAttribute(tgemm, cudaFuncAttributeMaxDynamicSharedMemorySize, TG_SMEM);
        attr_set = true;
    }

    const int q4blk = ((NTOK * ND) / 4 + 255) / 256;   // 4096
    const dim3 tg_grid(16, 16);

    // all splits (x + 6 weights) in one launch; beta from fp32 x
    split_all<<<dim3(q4blk, 7), 256>>>(x, Wq, Wk, Wv, Wa, Wg, Wo, xs, ws);
    beta_k<<<NTOK, 256>>>(x, Wb, bb, pbeta);

    // 5 input projections on tensor cores
    tgemm<<<tg_grid, 256, TG_SMEM>>>(xs, ws + 0 * WSTRIDE, nullptr, q0, 0);
    tgemm<<<tg_grid, 256, TG_SMEM>>>(xs, ws + 1 * WSTRIDE, nullptr, k0, 0);
    tgemm<<<tg_grid, 256, TG_SMEM>>>(xs, ws + 2 * WSTRIDE, nullptr, v0, 0);
    tgemm<<<tg_grid, 256, TG_SMEM>>>(xs, ws + 3 * WSTRIDE, ba,      pa, 1);
    tgemm<<<tg_grid, 256, TG_SMEM>>>(xs, ws + 4 * WSTRIDE, nullptr, pg, 1);

    // fused conv + silu (q, k*DK^-0.5, v)
    conv3<<<dim3(q4blk, 3), 256>>>(q0, k0, v0, conv_q_w, conv_k_w, conv_v_w,
                                   conv_q_b, conv_k_b, conv_v_b, qc, kc, vc);

    // recurrence (v-split 4x, deferred o-reduce) then LN + gate
    recur2<<<NB * NH * 4, 128>>>(qc, kc, vc, pa, pbeta, po4);
    ln_gate<<<NTOK * NH, 128>>>(po4, pg, ln_g, ln_b, pog);

    // output projection
    split4<<<q4blk, 256>>>(pog, xs, 0);
    tgemm<<<tg_grid, 256, TG_SMEM>>>(xs, ws + 5 * WSTRIDE, nullptr, out, 0);
}

// round 5
// speedup vs baseline: 2.9550x; 1.1259x over previous
#include <cuda_runtime.h>
#include <cuda_bf16.h>
#include <math.h>
#include <stdint.h>

#define NB   2
#define NT   1024
#define ND   2048
#define NH   16
#define NDK  128
#define NTOK (NB*NT)      /* 2048 tokens */
#define NC   (NH*NDK)     /* 2048 channels */
#define KS   (3*ND)       /* 6144: split-precision K (hi|lo|hi) */
#define WSTRIDE ((size_t)NC*KS)

// ------------------------------------------------------------------
// Scratch (device globals; no runtime allocation allowed)
// ------------------------------------------------------------------
__device__ __nv_bfloat16 g_xs[(size_t)NTOK*KS];   // split activations
__device__ __nv_bfloat16 g_ws[6*WSTRIDE];         // 6 split weights (q,k,v,a,g,o) contiguous
__device__ float g_q0[NTOK*NC];
__device__ float g_k0[NTOK*NC];
__device__ float g_v0[NTOK*NC];
__device__ float g_qc[NTOK*NC];
__device__ float g_kc[NTOK*NC];
__device__ float g_vc[NTOK*NC];
__device__ float g_a [NTOK*NC];
__device__ float g_gt[NTOK*NC];
__device__ float g_o4[(size_t)NTOK*NC*4];         // partial recurrence outputs
__device__ float g_bt[NTOK*NH];

// ==================================================================
// Helpers
// ==================================================================
__device__ __forceinline__ uint32_t smem_u32(const void* p) {
    uint32_t r;
    asm("{ .reg .u64 t; cvta.to.shared.u64 t, %1; cvt.u32.u64 %0, t; }"
        : "=r"(r) : "l"(p));
    return r;
}
__device__ __forceinline__ void cp16(uint32_t dst, const void* src) {
    asm volatile("cp.async.cg.shared.global [%0], [%1], 16;\n" :: "r"(dst), "l"(src));
}
__device__ __forceinline__ void cp_commit() {
    asm volatile("cp.async.commit_group;\n" ::: "memory");
}
__device__ __forceinline__ void cp_wait1() {
    asm volatile("cp.async.wait_group 1;\n" ::: "memory");
}
__device__ __forceinline__ void cp_wait0() {
    asm volatile("cp.async.wait_group 0;\n" ::: "memory");
}
__device__ __forceinline__ void ldsm4(uint32_t& r0, uint32_t& r1, uint32_t& r2,
                                      uint32_t& r3, uint32_t addr) {
    asm volatile("ldmatrix.sync.aligned.m8n8.x4.shared.b16 {%0,%1,%2,%3}, [%4];"
                 : "=r"(r0), "=r"(r1), "=r"(r2), "=r"(r3) : "r"(addr));
}
__device__ __forceinline__ void mma16816(float* d, const uint32_t* a,
                                         uint32_t b0, uint32_t b1) {
    asm volatile(
        "mma.sync.aligned.m16n8k16.row.col.f32.bf16.bf16.f32 "
        "{%0,%1,%2,%3}, {%4,%5,%6,%7}, {%8,%9}, {%0,%1,%2,%3};"
        : "+f"(d[0]), "+f"(d[1]), "+f"(d[2]), "+f"(d[3])
        : "r"(a[0]), "r"(a[1]), "r"(a[2]), "r"(a[3]), "r"(b0), "r"(b1));
}
__device__ __forceinline__ float fsig(float z) {
    return 1.f / (1.f + __expf(-z));
}

// ==================================================================
// Tensor-core GEMM (HMMA): one kernel serves
//   - fused 5-projection GEMM: grid.x = 80 (N = 10240 rows of g_ws)
//   - Wo GEMM: grid.x = 16 (seg always 0 -> plain store to Cq)
// 128x128 tile, BK = 64, 3-stage cp.async pipeline (96 KB smem), 8 warps.
// Segment (n0 >> 11) selects output buffer + epilogue:
//   seg 0..2 -> store (q0/k0/v0), seg 3 -> sigmoid(+ba) (a), seg 4 -> sigmoid (g)
// ==================================================================
#define BK      64
#define KITERS  (KS/BK)      /* 96 */
#define STG_B   32768        /* bytes per stage: A 16KB + B 16KB */
#define STAGES  3
#define TG_SMEM (STAGES*STG_B)

__global__ void __launch_bounds__(256, 2)
tgemm(const __nv_bfloat16* __restrict__ A, const __nv_bfloat16* __restrict__ Bw,
      const float* __restrict__ bias_a,
      float* __restrict__ Cq, float* __restrict__ Ck, float* __restrict__ Cv,
      float* __restrict__ Ca, float* __restrict__ Cg)
{
    extern __shared__ __align__(1024) char smem[];
    const uint32_t sb = smem_u32(smem);

    const int tid  = threadIdx.x;
    const int lane = tid & 31;
    const int wid  = tid >> 5;
    const int wm   = wid & 3;            // 4 warps along m
    const int wn   = wid >> 2;           // 2 warps along n
    const int m0   = blockIdx.y * 128;
    const int n0g  = blockIdx.x * 128;   // global weight-row offset (0..10239)
    const int seg  = blockIdx.x >> 4;    // 0..4
    const int col0 = (blockIdx.x & 15) * 128;

    // ---- load-side addressing: tile = 128 rows x 128 bytes, SW128 swizzle
    const int r0 = tid >> 3;             // row 0..31 (stride 32)
    const int c0 = tid & 7;              // 16B chunk 0..7
    const uint32_t stOff = (uint32_t)(((c0 ^ (r0 & 7)) << 4));

    const __nv_bfloat16* gA = A  + (size_t)(m0  + r0) * KS + c0 * 8;
    const __nv_bfloat16* gB = Bw + (size_t)(n0g + r0) * KS + c0 * 8;

    // ---- mma-side addressing (byte offsets inside a stage)
    const int la = lane & 15, ha = lane >> 4;
    const int arow = wm * 32 + la;
    const uint32_t aswz = arow & 7;
    const int brow = wn * 64 + (lane & 7) + ((lane >> 4) & 1) * 8;
    const uint32_t bswz = brow & 7;
    const uint32_t bsel = (lane >> 3) & 1;

    uint32_t aoff[4], boff[4];
#pragma unroll
    for (int kh = 0; kh < 4; kh++) {
        aoff[kh] = arow * 128 + (((uint32_t)((2 * kh + ha) ^ aswz)) << 4);
        boff[kh] = 16384 + brow * 128 + (((uint32_t)((2 * kh + bsel) ^ bswz)) << 4);
    }

    float acc[2][8][4];
#pragma unroll
    for (int mi = 0; mi < 2; mi++)
#pragma unroll
        for (int ni = 0; ni < 8; ni++)
#pragma unroll
            for (int e = 0; e < 4; e++) acc[mi][ni][e] = 0.f;

    // ---- prologue: stages 0,1
#pragma unroll
    for (int s = 0; s < STAGES - 1; s++) {
        const uint32_t base = sb + s * STG_B;
        const int kc = s * BK;
#pragma unroll
        for (int r = 0; r < 4; r++) {
            const uint32_t so = (r0 + 32 * r) * 128 + stOff;
            cp16(base + so,         gA + (size_t)(32 * r) * KS + kc);
            cp16(base + 16384 + so, gB + (size_t)(32 * r) * KS + kc);
        }
        cp_commit();
    }

    int stage = 0;
    for (int it = 0; it < KITERS; it++) {
        if (it < KITERS - 1) cp_wait1(); else cp_wait0();
        __syncthreads();

        if (it + 2 < KITERS) {
            const int ps = (stage + 2 >= STAGES) ? stage + 2 - STAGES : stage + 2;
            const uint32_t base = sb + ps * STG_B;
            const int kc = (it + 2) * BK;
#pragma unroll
            for (int r = 0; r < 4; r++) {
                const uint32_t so = (r0 + 32 * r) * 128 + stOff;
                cp16(base + so,         gA + (size_t)(32 * r) * KS + kc);
                cp16(base + 16384 + so, gB + (size_t)(32 * r) * KS + kc);
            }
        }
        cp_commit();

        const uint32_t base = sb + stage * STG_B;
        stage = (stage + 1 >= STAGES) ? 0 : stage + 1;

#pragma unroll
        for (int kh = 0; kh < 4; kh++) {
            uint32_t av[2][4];
            ldsm4(av[0][0], av[0][1], av[0][2], av[0][3], base + aoff[kh]);
            ldsm4(av[1][0], av[1][1], av[1][2], av[1][3], base + aoff[kh] + 2048);

            uint32_t bv[4][4];
#pragma unroll
            for (int p = 0; p < 4; p++)
                ldsm4(bv[p][0], bv[p][1], bv[p][2], bv[p][3],
                      base + boff[kh] + p * 2048);

#pragma unroll
            for (int mi = 0; mi < 2; mi++)
#pragma unroll
                for (int ni = 0; ni < 8; ni++) {
                    const int p = ni >> 1;
                    const int h = (ni & 1) * 2;
                    mma16816(acc[mi][ni], av[mi], bv[p][h], bv[p][h + 1]);
                }
        }
    }

    // ---- epilogue: segment select
    float* C = (seg == 0) ? Cq : (seg == 1) ? Ck : (seg == 2) ? Cv
             : (seg == 3) ? Ca : Cg;
    const int et = (seg == 3) ? 1 : (seg == 4) ? 2 : 0;

    const int g  = lane >> 2;
    const int tg = lane & 3;
#pragma unroll
    for (int mi = 0; mi < 2; mi++) {
        const int row = m0 + wm * 32 + mi * 16 + g;
#pragma unroll
        for (int ni = 0; ni < 8; ni++) {
            const int col = col0 + wn * 64 + ni * 8 + tg * 2;
            float v0 = acc[mi][ni][0], v1 = acc[mi][ni][1];
            float v2 = acc[mi][ni][2], v3 = acc[mi][ni][3];
            if (et == 1) {
                const float b0 = bias_a[col], b1 = bias_a[col + 1];
                v0 = fsig(v0 + b0); v1 = fsig(v1 + b1);
                v2 = fsig(v2 + b0); v3 = fsig(v3 + b1);
            } else if (et == 2) {
                v0 = fsig(v0); v1 = fsig(v1); v2 = fsig(v2); v3 = fsig(v3);
            }
            *(float2*)(C + (size_t)row * NC + col)       = make_float2(v0, v1);
            *(float2*)(C + (size_t)(row + 8) * NC + col) = make_float2(v2, v3);
        }
    }
}

// ------------------------------------------------------------------
// Split fp32 -> bf16 hi/lo, K-concatenated (float4 vectorized).
// mode 0 (activation): [hi | lo | hi]   mode 1 (weight): [hi | hi | lo]
// ------------------------------------------------------------------
__device__ __forceinline__ void split_body(const float* __restrict__ in,
                                           __nv_bfloat16* __restrict__ out,
                                           int mode, int i /* float4 index */)
{
    const int r  = i >> 9;
    const int k4 = (i << 2) & 2047;
    const float4 a = ((const float4*)in)[i];

    __nv_bfloat162 h01 = __floats2bfloat162_rn(a.x, a.y);
    __nv_bfloat162 h23 = __floats2bfloat162_rn(a.z, a.w);
    const float lx = a.x - __bfloat162float(__low2bfloat16(h01));
    const float ly = a.y - __bfloat162float(__high2bfloat16(h01));
    const float lz = a.z - __bfloat162float(__low2bfloat16(h23));
    const float lw = a.w - __bfloat162float(__high2bfloat16(h23));
    __nv_bfloat162 l01 = __floats2bfloat162_rn(lx, ly);
    __nv_bfloat162 l23 = __floats2bfloat162_rn(lz, lw);

    uint2 hp, lp;
    hp.x = *(const uint32_t*)&h01; hp.y = *(const uint32_t*)&h23;
    lp.x = *(const uint32_t*)&l01; lp.y = *(const uint32_t*)&l23;

    __nv_bfloat16* base = out + (size_t)r * KS + k4;
    *(uint2*)(base) = hp;
    if (mode == 0) { *(uint2*)(base + 2048) = lp; *(uint2*)(base + 4096) = hp; }
    else           { *(uint2*)(base + 2048) = hp; *(uint2*)(base + 4096) = lp; }
}

__global__ void __launch_bounds__(256)
split_all(const float* __restrict__ x,  const float* __restrict__ Wq,
          const float* __restrict__ Wk, const float* __restrict__ Wv,
          const float* __restrict__ Wa, const float* __restrict__ Wg,
          const float* __restrict__ Wo,
          __nv_bfloat16* __restrict__ xs, __nv_bfloat16* __restrict__ ws)
{
    const int i = blockIdx.x * 256 + threadIdx.x;
    if (i >= (NTOK * ND) / 4) return;
    const int which = blockIdx.y;
    if (which == 0)      split_body(x,  xs, 0, i);
    else if (which == 1) split_body(Wq, ws + 0 * WSTRIDE, 1, i);
    else if (which == 2) split_body(Wk, ws + 1 * WSTRIDE, 1, i);
    else if (which == 3) split_body(Wv, ws + 2 * WSTRIDE, 1, i);
    else if (which == 4) split_body(Wa, ws + 3 * WSTRIDE, 1, i);
    else if (which == 5) split_body(Wg, ws + 4 * WSTRIDE, 1, i);
    else                 split_body(Wo, ws + 5 * WSTRIDE, 1, i);
}

// ------------------------------------------------------------------
// beta = sigmoid(x @ Wb^T + bb)
// ------------------------------------------------------------------
__global__ void __launch_bounds__(256)
beta_k(const float* __restrict__ x, const float* __restrict__ Wb,
       const float* __restrict__ bb, float* __restrict__ out)
{
    __shared__ float xs[ND];
    const int row = blockIdx.x;
    for (int i = threadIdx.x; i < ND; i += 256) xs[i] = x[(size_t)row * ND + i];
    __syncthreads();
    const int w = threadIdx.x >> 5, lane = threadIdx.x & 31;
    for (int h = w; h < NH; h += 8) {
        const float* wr = Wb + (size_t)h * ND;
        float s = 0.f;
        for (int i = lane; i < ND; i += 32) s = fmaf(xs[i], wr[i], s);
#pragma unroll
        for (int o = 16; o > 0; o >>= 1) s += __shfl_xor_sync(0xffffffffu, s, o);
        if (lane == 0) out[(size_t)row * NH + h] = fsig(s + bb[h]);
    }
}

// ------------------------------------------------------------------
// Fused causal depthwise conv (K=4) + bias + silu + scale, float4, q/k/v
// ------------------------------------------------------------------
__global__ void __launch_bounds__(256)
conv3(const float* __restrict__ q0, const float* __restrict__ k0,
      const float* __restrict__ v0,
      const float* __restrict__ wq, const float* __restrict__ wk,
      const float* __restrict__ wv,
      const float* __restrict__ bq, const float* __restrict__ bk,
      const float* __restrict__ bv,
      float* __restrict__ qc, float* __restrict__ kc, float* __restrict__ vc)
{
    const int i = blockIdx.x * 256 + threadIdx.x;
    if (i >= (NTOK * NC) / 4) return;

    const float* in; const float* w; const float* bias; float* out; float scale;
    if (blockIdx.y == 0)      { in = q0; w = wq; bias = bq; out = qc; scale = 1.f; }
    else if (blockIdx.y == 1) { in = k0; w = wk; bias = bk; out = kc; scale = 0.08838834764831845f; }
    else                      { in = v0; w = wv; bias = bv; out = vc; scale = 1.f; }

    const int c  = (i << 2) & (NC - 1);
    const int bt = (i << 2) >> 11;
    const int t  = bt & (NT - 1);

    const float4 w0 = ((const float4*)w)[c + 0];
    const float4 w1 = ((const float4*)w)[c + 1];
    const float4 w2 = ((const float4*)w)[c + 2];
    const float4 w3 = ((const float4*)w)[c + 3];
    const float* p = in + (size_t)bt * NC + c;

    float4 acc = *(const float4*)(bias + c);
    float4 xv = *(const float4*)p;
    acc.x = fmaf(w0.w, xv.x, acc.x); acc.y = fmaf(w1.w, xv.y, acc.y);
    acc.z = fmaf(w2.w, xv.z, acc.z); acc.w = fmaf(w3.w, xv.w, acc.w);
    if (t >= 1) {
        xv = *(const float4*)(p - NC);
        acc.x = fmaf(w0.z, xv.x, acc.x); acc.y = fmaf(w1.z, xv.y, acc.y);
        acc.z = fmaf(w2.z, xv.z, acc.z); acc.w = fmaf(w3.z, xv.w, acc.w);
    }
    if (t >= 2) {
        xv = *(const float4*)(p - 2 * NC);
        acc.x = fmaf(w0.y, xv.x, acc.x); acc.y = fmaf(w1.y, xv.y, acc.y);
        acc.z = fmaf(w2.y, xv.z, acc.z); acc.w = fmaf(w3.y, xv.w, acc.w);
    }
    if (t >= 3) {
        xv = *(const float4*)(p - 3 * NC);
        acc.x = fmaf(w0.x, xv.x, acc.x); acc.y = fmaf(w1.x, xv.y, acc.y);
        acc.z = fmaf(w2.x, xv.z, acc.z); acc.w = fmaf(w3.x, xv.w, acc.w);
    }
    float4 r;
    r.x = acc.x * fsig(acc.x) * scale;
    r.y = acc.y * fsig(acc.y) * scale;
    r.z = acc.z * fsig(acc.z) * scale;
    r.w = acc.w * fsig(acc.w) * scale;
    *(float4*)(out + (size_t)bt * NC + c) = r;
}

// ------------------------------------------------------------------
// Recurrence, v-split 4x, deferred o-reduction.
// ------------------------------------------------------------------
__global__ void __launch_bounds__(128)
recur2(const float* __restrict__ qc, const float* __restrict__ kc,
       const float* __restrict__ vc, const float* __restrict__ ga,
       const float* __restrict__ gbeta, float* __restrict__ o4)
{
    const int bid  = blockIdx.x;
    const int b    = bid >> 6;
    const int h    = (bid >> 2) & 15;
    const int vblk = bid & 3;
    const int tid  = threadIdx.x;
    const int vloc = tid >> 2;
    const int kq   = tid & 3;

    __shared__ __align__(16) float sk[2][160];
    __shared__ __align__(16) float sq[2][160];

    float S[32];
#pragma unroll
    for (int j = 0; j < 32; j++) S[j] = 0.f;

    const int kchan = h * NDK + tid;
    const int vchan = h * NDK + vblk * 32 + vloc;
    const int sidx  = (tid >> 5) * 40 + (tid & 31);
    const size_t tok0 = (size_t)b * NT;

    float k_cur = kc[tok0 * NC + kchan];
    float q_cur = qc[tok0 * NC + kchan];
    float v_cur = vc[tok0 * NC + vchan];
    float a_cur = ga[tok0 * NC + vchan];
    float be_cur = gbeta[tok0 * NH + h];

    for (int t = 0; t < NT; t++) {
        const int buf = t & 1;
        sk[buf][sidx] = k_cur;
        sq[buf][sidx] = q_cur;
        __syncthreads();

        float k_n = 0.f, q_n = 0.f, v_n = 0.f, a_n = 0.f, be_n = 0.f;
        if (t + 1 < NT) {
            const size_t idx = (tok0 + t + 1) * NC;
            k_n = kc[idx + kchan]; q_n = qc[idx + kchan];
            v_n = vc[idx + vchan]; a_n = ga[idx + vchan];
            be_n = gbeta[(tok0 + t + 1) * NH + h];
        }

        const float4* kb = (const float4*)&sk[buf][kq * 40];
        const float4* qb = (const float4*)&sq[buf][kq * 40];

        float p0 = 0.f, p1 = 0.f, p2 = 0.f, p3 = 0.f;
        float p4 = 0.f, p5 = 0.f, p6 = 0.f, p7 = 0.f;
#pragma unroll
        for (int j = 0; j < 4; j++) {
            const float4 ka = kb[2 * j];
            const float4 kc2 = kb[2 * j + 1];
            p0 = fmaf(S[8*j+0], ka.x,  p0);
            p1 = fmaf(S[8*j+1], ka.y,  p1);
            p2 = fmaf(S[8*j+2], ka.z,  p2);
            p3 = fmaf(S[8*j+3], ka.w,  p3);
            p4 = fmaf(S[8*j+4], kc2.x, p4);
            p5 = fmaf(S[8*j+5], kc2.y, p5);
            p6 = fmaf(S[8*j+6], kc2.z, p6);
            p7 = fmaf(S[8*j+7], kc2.w, p7);
        }
        float Sk = ((p0 + p1) + (p2 + p3)) + ((p4 + p5) + (p6 + p7));
        Sk += __shfl_xor_sync(0xffffffffu, Sk, 1);
        Sk += __shfl_xor_sync(0xffffffffu, Sk, 2);

        const float coef = be_cur * (Sk - v_cur);
        const float a = a_cur;

        float o0 = 0.f, o1 = 0.f, o2 = 0.f, o3 = 0.f;
        float o4r = 0.f, o5 = 0.f, o6 = 0.f, o7 = 0.f;
#pragma unroll
        for (int j = 0; j < 4; j++) {
            const float4 ka  = kb[2 * j];
            const float4 kc2 = kb[2 * j + 1];
            const float4 qa  = qb[2 * j];
            const float4 qc2 = qb[2 * j + 1];
            S[8*j+0] = fmaf(a, S[8*j+0], -coef * ka.x);  o0  = fmaf(S[8*j+0], qa.x,  o0);
            S[8*j+1] = fmaf(a, S[8*j+1], -coef * ka.y);  o1  = fmaf(S[8*j+1], qa.y,  o1);
            S[8*j+2] = fmaf(a, S[8*j+2], -coef * ka.z);  o2  = fmaf(S[8*j+2], qa.z,  o2);
            S[8*j+3] = fmaf(a, S[8*j+3], -coef * ka.w);  o3  = fmaf(S[8*j+3], qa.w,  o3);
            S[8*j+4] = fmaf(a, S[8*j+4], -coef * kc2.x); o4r = fmaf(S[8*j+4], qc2.x, o4r);
            S[8*j+5] = fmaf(a, S[8*j+5], -coef * kc2.y); o5  = fmaf(S[8*j+5], qc2.y, o5);
            S[8*j+6] = fmaf(a, S[8*j+6], -coef * kc2.z); o6  = fmaf(S[8*j+6], qc2.z, o6);
            S[8*j+7] = fmaf(a, S[8*j+7], -coef * kc2.w); o7  = fmaf(S[8*j+7], qc2.w, o7);
        }
        const float op = ((o0 + o1) + (o2 + o3)) + ((o4r + o5) + (o6 + o7));
        o4[((tok0 + t) * NC + vchan) * 4 + kq] = op;

        k_cur = k_n; q_cur = q_n; v_cur = v_n; a_cur = a_n; be_cur = be_n;
    }
}

// ------------------------------------------------------------------
// Sum 4 partials + LayerNorm + gate + bf16 split directly into g_xs.
// grid = NTOK*NH, block = 128
// ------------------------------------------------------------------
__global__ void __launch_bounds__(128)
ln_gate_split(const float* __restrict__ o4, const float* __restrict__ gg,
              const float* __restrict__ ln_g, const float* __restrict__ ln_b,
              __nv_bfloat16* __restrict__ xs)
{
    const int bid = blockIdx.x;
    const int tok = bid >> 4, h = bid & 15;
    const int v = threadIdx.x, lane = v & 31, wid = v >> 5;
    const int chan = h * NDK + v;
    const size_t idx = (size_t)tok * NC + chan;

    const float4 part = ((const float4*)o4)[idx];
    const float o = (part.x + part.y) + (part.z + part.w);

    __shared__ float red[8];
    float rs = o, rs2 = o * o;
#pragma unroll
    for (int off = 16; off > 0; off >>= 1) {
        rs  += __shfl_xor_sync(0xffffffffu, rs,  off);
        rs2 += __shfl_xor_sync(0xffffffffu, rs2, off);
    }
    if (lane == 0) { red[wid] = rs; red[4 + wid] = rs2; }
    __syncthreads();
    const float mu  = (red[0] + red[1] + red[2] + red[3]) * (1.f / 128.f);
    const float ms  = (red[4] + red[5] + red[6] + red[7]) * (1.f / 128.f);
    const float var = ms - mu * mu;
    const float y = ((o - mu) * rsqrtf(var + 1e-5f) * ln_g[v] + ln_b[v]) * gg[idx];

    const __nv_bfloat16 hbf = __float2bfloat16(y);
    const __nv_bfloat16 lbf = __float2bfloat16(y - __bfloat162float(hbf));
    __nv_bfloat16* base = xs + (size_t)tok * KS + chan;
    base[0]    = hbf;
    base[2048] = lbf;
    base[4096] = hbf;
}

// ------------------------------------------------------------------
// Launch
// ------------------------------------------------------------------
extern "C" void kernel_launch(void* const* d_in, const int* in_sizes, int n_in,
                              void* d_out, int out_size)
{
    const float* x        = (const float*)d_in[0];
    const float* Wq       = (const float*)d_in[1];
    const float* Wk       = (const float*)d_in[2];
    const float* Wv       = (const float*)d_in[3];
    const float* Wa       = (const float*)d_in[4];
    const float* ba       = (const float*)d_in[5];
    const float* Wb       = (const float*)d_in[6];
    const float* bb       = (const float*)d_in[7];
    const float* conv_q_w = (const float*)d_in[8];
    const float* conv_q_b = (const float*)d_in[9];
    const float* conv_k_w = (const float*)d_in[10];
    const float* conv_k_b = (const float*)d_in[11];
    const float* conv_v_w = (const float*)d_in[12];
    const float* conv_v_b = (const float*)d_in[13];
    const float* Wg       = (const float*)d_in[14];
    const float* ln_g     = (const float*)d_in[15];
    const float* ln_b     = (const float*)d_in[16];
    const float* Wo       = (const float*)d_in[17];
    float* out = (float*)d_out;

    __nv_bfloat16 *xs, *ws;
    float *q0, *k0, *v0, *qc, *kc, *vc, *pa, *pg, *po4, *pbeta;
    cudaGetSymbolAddress((void**)&xs,    g_xs);
    cudaGetSymbolAddress((void**)&ws,    g_ws);
    cudaGetSymbolAddress((void**)&q0,    g_q0);
    cudaGetSymbolAddress((void**)&k0,    g_k0);
    cudaGetSymbolAddress((void**)&v0,    g_v0);
    cudaGetSymbolAddress((void**)&qc,    g_qc);
    cudaGetSymbolAddress((void**)&kc,    g_kc);
    cudaGetSymbolAddress((void**)&vc,    g_vc);
    cudaGetSymbolAddress((void**)&pa,    g_a);
    cudaGetSymbolAddress((void**)&pg,    g_gt);
    cudaGetSymbolAddress((void**)&po4,   g_o4);
    cudaGetSymbolAddress((void**)&pbeta, g_bt);

    static bool attr_set = false;
    if (!attr_set) {
        cudaFuncSetAttribute(tgemm, cudaFuncAttributeMaxDynamicSharedMemorySize, TG_SMEM);
        attr_set = true;
    }

    const int q4blk = ((NTOK * ND) / 4 + 255) / 256;   // 4096

    // all splits (x + 6 weights) in one launch; beta from fp32 x
    split_all<<<dim3(q4blk, 7), 256>>>(x, Wq, Wk, Wv, Wa, Wg, Wo, xs, ws);
    beta_k<<<NTOK, 256>>>(x, Wb, bb, pbeta);

    // fused 5-projection GEMM (q, k, v, a, g) — N = 10240
    tgemm<<<dim3(80, 16), 256, TG_SMEM>>>(xs, ws, ba, q0, k0, v0, pa, pg);

    // fused conv + silu (q, k*DK^-0.5, v)
    conv3<<<dim3(q4blk, 3), 256>>>(q0, k0, v0, conv_q_w, conv_k_w, conv_v_w,
                                   conv_q_b, conv_k_b, conv_v_b, qc, kc, vc);

    // recurrence (v-split 4x, deferred o-reduce) then LN + gate + split into xs
    recur2<<<NB * NH * 4, 128>>>(qc, kc, vc, pa, pbeta, po4);
    ln_gate_split<<<NTOK * NH, 128>>>(po4, pg, ln_g, ln_b, xs);

    // output projection (seg = 0 -> plain store to out)
    tgemm<<<dim3(16, 16), 256, TG_SMEM>>>(xs, ws + 5 * WSTRIDE, nullptr,
                                          out, out, out, out, out);
}